// round 7
// baseline (speedup 1.0000x reference)
#include <cuda_runtime.h>
#include <math.h>

// Problem constants
#define NSEQ 32
#define NHEAD 32
#define NKV 8
#define HPG 4            // heads per kv head (GQA)
#define DH 128           // head size
#define BS 16            // tokens per block
#define MAXB 256         // max blocks per seq
#define CB 16            // blocks per chunk
#define CT (CB * BS)     // 256 tokens per chunk
#define NCHUNK 16
#define NITEMS (NCHUNK * NKV * NSEQ)   // 4096
#define QK_SCALE 0.08838834764831845f
#define RPITCH 10        // padded pitch for partial-reduction smem
#define NCTAS 296        // 148 SMs x 2 resident CTAs

// Split-KV partial scratch (allocation-free: __device__ globals)
__device__ float  g_pacc[NSEQ * NKV * NCHUNK * HPG * DH];   // 8 MB
__device__ float2 g_pml [NSEQ * NKV * NCHUNK * HPG];
__device__ int    g_ctr;                                    // zero-init; reset by combine

__global__ __launch_bounds__(256, 2) void pa_chunk_kernel(
    const float* __restrict__ q,    // [S, 32, 128]
    const float* __restrict__ kc,   // [NB, 8, 16, 16, 8]  per (b,g): 2048 contig floats
    const float* __restrict__ vc,   // [NB, 8, 128, 16]    per (b,g): 2048 contig floats
    const int*   __restrict__ bt,   // [S, 256]
    const int*   __restrict__ cl)   // [S]
{
    const int tid = threadIdx.x;
    const int w = tid >> 5, l = tid & 31;

    __shared__ __align__(16) float q_s[HPG * DH];            // 2 KB
    __shared__ __align__(16) float ls[HPG * CT];             // 4 KB: logits then probs
    __shared__ __align__(16) float red_s[512 * RPITCH];      // 20 KB partials (8-blk groups)
    __shared__ float red[8], red2[8];
    __shared__ int bt_s[CB];
    __shared__ int item_s;

    for (;;) {
        // ---- grab next non-empty work item (tid 0 skips empties cheaply) ----
        if (tid == 0) {
            int it;
            for (;;) {
                it = atomicAdd(&g_ctr, 1);
                if (it >= NITEMS) break;
                const int ss = (it >> 3) & 31;
                const int cc = it >> 8;
                if (cc * CT < cl[ss]) break;
            }
            item_s = it;
        }
        __syncthreads();   // broadcast item; also protects smem reuse across items
        const int item = item_s;
        if (item >= NITEMS) return;

        const int c = item >> 8;
        const int s = (item >> 3) & 31;
        const int g = item & 7;
        const int len = cl[s];
        const int n_tok = min(len - c * CT, CT);
        const int n_blk = (n_tok + BS - 1) / BS;

        if (tid < CB) bt_s[tid] = bt[s * MAXB + c * CB + tid];
        if (tid < 128)
            ((float4*)q_s)[tid] =
                ((const float4*)(q + ((size_t)s * NHEAD + g * HPG) * DH))[tid];
        __syncthreads();

        // ===== Phase 1: K stream, lane-contiguous LDGs, 4-deep pipeline,
        //       reduce in groups of 8 blocks (4 barriers/item) ================
        {
            float4 qreg[HPG][2];
            {
                const int dbase = w * 16 + (l & 1) * 4;
#pragma unroll
                for (int h = 0; h < HPG; h++) {
                    qreg[h][0] = *(const float4*)&q_s[h * DH + dbase];
                    qreg[h][1] = *(const float4*)&q_s[h * DH + dbase + 8];
                }
            }
            const int koff = w * 256 + l * 4;
            const int tok = l >> 1;

            float4 kb[4][2];
#pragma unroll
            for (int p = 0; p < 4; p++) {
                const int bp = min(p, n_blk - 1);
                const float* sp = kc + ((size_t)bt_s[bp] * NKV + g) * 2048 + koff;
                kb[p][0] = *(const float4*)sp;
                kb[p][1] = *(const float4*)(sp + 128);
            }

#pragma unroll 1
            for (int gi = 0; gi < n_blk; gi += 8) {
#pragma unroll
                for (int uu = 0; uu < 8; uu++) {
                    if (gi + uu < n_blk) {
                        const int slot = uu & 3;
                        const float4 a0 = kb[slot][0], a1 = kb[slot][1];
                        const int np = min(gi + uu + 4, n_blk - 1);
                        const float* sp = kc + ((size_t)bt_s[np] * NKV + g) * 2048 + koff;
                        kb[slot][0] = *(const float4*)sp;
                        kb[slot][1] = *(const float4*)(sp + 128);
#pragma unroll
                        for (int h = 0; h < HPG; h++) {
                            float t = 0.f;
                            t = fmaf(a0.x, qreg[h][0].x, t); t = fmaf(a0.y, qreg[h][0].y, t);
                            t = fmaf(a0.z, qreg[h][0].z, t); t = fmaf(a0.w, qreg[h][0].w, t);
                            t = fmaf(a1.x, qreg[h][1].x, t); t = fmaf(a1.y, qreg[h][1].y, t);
                            t = fmaf(a1.z, qreg[h][1].z, t); t = fmaf(a1.w, qreg[h][1].w, t);
                            t += __shfl_xor_sync(0xffffffffu, t, 1);
                            if ((l & 1) == 0)
                                red_s[((uu * HPG + h) * BS + tok) * RPITCH + w] = t;
                        }
                    }
                }
                __syncthreads();
#pragma unroll
                for (int e = tid; e < 512; e += 256) {
                    const int blk_u = e >> 6;
                    const int hh = (e >> 4) & 3;
                    const int tk = e & 15;
                    if (gi + blk_u < n_blk) {
                        const float* rp = &red_s[e * RPITCH];
                        float sum = 0.f;
#pragma unroll
                        for (int j = 0; j < 8; j++) sum += rp[j];
                        ls[hh * CT + (gi + blk_u) * BS + tk] = sum;
                    }
                }
                __syncthreads();
            }
        }

        // ===== Hoisted V prologue: keep DRAM busy through the softmax =======
        const int tl = (l & 3) * 4;
        const int d0 = w * 16 + (l >> 2);
        const int voff = w * 256 + l * 4;
        float4 vb[4][2];
#pragma unroll
        for (int p = 0; p < 4; p++) {
            const int bp = min(p, n_blk - 1);
            const float* sp = vc + ((size_t)bt_s[bp] * NKV + g) * 2048 + voff;
            vb[p][0] = *(const float4*)sp;
            vb[p][1] = *(const float4*)(sp + 128);
        }

        // ===== Phase 2: one-shot softmax over the chunk =====================
        const int h2 = tid >> 6;
        const int t2 = tid & 63;
        {
            float vals[4];
            float lmax = -1e30f;
#pragma unroll
            for (int k = 0; k < 4; k++) {
                const int tok = t2 + 64 * k;
                vals[k] = (tok < n_tok) ? ls[h2 * CT + tok] * QK_SCALE : -1e30f;
                lmax = fmaxf(lmax, vals[k]);
            }
#pragma unroll
            for (int o = 1; o < 32; o <<= 1)
                lmax = fmaxf(lmax, __shfl_xor_sync(0xffffffffu, lmax, o));
            if ((tid & 31) == 0) red[tid >> 5] = lmax;
            __syncthreads();
            const float m = fmaxf(red[h2 * 2], red[h2 * 2 + 1]);
            float lsum = 0.f;
#pragma unroll
            for (int k = 0; k < 4; k++) {
                const int tok = t2 + 64 * k;
                const float p = (tok < n_tok) ? __expf(vals[k] - m) : 0.f;
                ls[h2 * CT + tok] = p;
                lsum += p;
            }
#pragma unroll
            for (int o = 1; o < 32; o <<= 1)
                lsum += __shfl_xor_sync(0xffffffffu, lsum, o);
            if ((tid & 31) == 0) red2[tid >> 5] = lsum;
            __syncthreads();
            if (t2 == 0) {
                const int base = ((s * NKV + g) * NCHUNK + c) * HPG;
                g_pml[base + h2] = make_float2(m, red2[h2 * 2] + red2[h2 * 2 + 1]);
            }
        }

        // ===== Phase 3: V stream, lane-contiguous, 4-block pipeline =========
        {
            float acc[HPG][2] = {};
            int i = 0;
#pragma unroll 1
            for (; i + 4 <= n_blk; i += 4) {
#pragma unroll
                for (int u = 0; u < 4; u++) {
                    const float4 a0 = vb[u][0], a1 = vb[u][1];
                    const int np = min(i + u + 4, n_blk - 1);
                    const float* sp = vc + ((size_t)bt_s[np] * NKV + g) * 2048 + voff;
                    vb[u][0] = *(const float4*)sp;
                    vb[u][1] = *(const float4*)(sp + 128);
                    const int pbase = (i + u) * BS + tl;
#pragma unroll
                    for (int h = 0; h < HPG; h++) {
                        const float4 pv = *(const float4*)&ls[h * CT + pbase];
                        float a = acc[h][0];
                        a = fmaf(a0.x, pv.x, a); a = fmaf(a0.y, pv.y, a);
                        a = fmaf(a0.z, pv.z, a); a = fmaf(a0.w, pv.w, a);
                        acc[h][0] = a;
                        float b = acc[h][1];
                        b = fmaf(a1.x, pv.x, b); b = fmaf(a1.y, pv.y, b);
                        b = fmaf(a1.z, pv.z, b); b = fmaf(a1.w, pv.w, b);
                        acc[h][1] = b;
                    }
                }
            }
#pragma unroll
            for (int u = 0; u < 3; u++) {
                if (i + u < n_blk) {
                    const float4 a0 = vb[u][0], a1 = vb[u][1];
                    const int pbase = (i + u) * BS + tl;
#pragma unroll
                    for (int h = 0; h < HPG; h++) {
                        const float4 pv = *(const float4*)&ls[h * CT + pbase];
                        float a = acc[h][0];
                        a = fmaf(a0.x, pv.x, a); a = fmaf(a0.y, pv.y, a);
                        a = fmaf(a0.z, pv.z, a); a = fmaf(a0.w, pv.w, a);
                        acc[h][0] = a;
                        float b = acc[h][1];
                        b = fmaf(a1.x, pv.x, b); b = fmaf(a1.y, pv.y, b);
                        b = fmaf(a1.z, pv.z, b); b = fmaf(a1.w, pv.w, b);
                        acc[h][1] = b;
                    }
                }
            }
            const int base = ((s * NKV + g) * NCHUNK + c) * HPG;
#pragma unroll
            for (int h = 0; h < HPG; h++) {
#pragma unroll
                for (int r = 0; r < 2; r++) {
                    float v = acc[h][r];
                    v += __shfl_xor_sync(0xffffffffu, v, 1);
                    v += __shfl_xor_sync(0xffffffffu, v, 2);
                    if ((l & 3) == 0)
                        g_pacc[(size_t)(base + h) * DH + d0 + r * 8] = v;
                }
            }
        }
    }
}

__global__ __launch_bounds__(128) void pa_combine_kernel(
    const int* __restrict__ cl, float* __restrict__ out)
{
    // reset work-stealing counter for the next replay (stream-ordered, race-free)
    if (blockIdx.x == 0 && blockIdx.y == 0 && threadIdx.x == 0) g_ctr = 0;

    const int h = blockIdx.x, s = blockIdx.y;
    const int g = h >> 2, hh = h & 3;
    const int d = threadIdx.x;
    const int len = cl[s];
    const int nc = min(NCHUNK, (len + CT - 1) / CT);
    const int base = (s * NKV + g) * NCHUNK;

    float2 ml[NCHUNK];
    float M = -1e30f;
#pragma unroll
    for (int c = 0; c < NCHUNK; c++) {
        ml[c] = (c < nc) ? g_pml[(base + c) * HPG + hh] : make_float2(-1e30f, 0.f);
        M = fmaxf(M, ml[c].x);
    }
    float pa[NCHUNK];
#pragma unroll
    for (int c = 0; c < NCHUNK; c++)
        pa[c] = (c < nc) ? g_pacc[(size_t)((base + c) * HPG + hh) * DH + d] : 0.f;
    float L = 0.f, o = 0.f;
#pragma unroll
    for (int c = 0; c < NCHUNK; c++) {
        const float wgt = __expf(ml[c].x - M);
        L += ml[c].y * wgt;
        o += pa[c] * wgt;
    }
    out[((size_t)s * NHEAD + h) * DH + d] = o / L;
}

extern "C" void kernel_launch(void* const* d_in, const int* in_sizes, int n_in,
                              void* d_out, int out_size)
{
    const float* q  = (const float*)d_in[0];
    const float* kc = (const float*)d_in[1];
    const float* vc = (const float*)d_in[2];
    const int*   bt = (const int*)d_in[3];
    const int*   cl = (const int*)d_in[4];
    float* out = (float*)d_out;

    pa_chunk_kernel<<<NCTAS, 256>>>(q, kc, vc, bt, cl);   // persistent, work-stealing
    dim3 grid2(NHEAD, NSEQ);                              // 32 x 32 = 1024 CTAs
    pa_combine_kernel<<<grid2, 128>>>(cl, out);
}

// round 8
// speedup vs baseline: 1.1073x; 1.1073x over previous
#include <cuda_runtime.h>
#include <math.h>

// Problem constants
#define NSEQ 32
#define NHEAD 32
#define NKV 8
#define HPG 4            // heads per kv head (GQA)
#define DH 128           // head size
#define BS 16            // tokens per block
#define MAXB 256         // max blocks per seq
#define CB 16            // blocks per chunk
#define CT (CB * BS)     // 256 tokens per chunk
#define NCHUNK 16
#define QK_SCALE 0.08838834764831845f
#define RPITCH 10        // padded pitch for partial-reduction smem

// Split-KV partial scratch (allocation-free: __device__ globals)
__device__ float  g_pacc[NSEQ * NKV * NCHUNK * HPG * DH];   // 8 MB
__device__ float2 g_pml [NSEQ * NKV * NCHUNK * HPG];

__global__ __launch_bounds__(256, 3) void pa_chunk_kernel(
    const float* __restrict__ q,    // [S, 32, 128]
    const float* __restrict__ kc,   // [NB, 8, 16, 16, 8]  per (b,g): 2048 contig floats
    const float* __restrict__ vc,   // [NB, 8, 128, 16]    per (b,g): 2048 contig floats
    const int*   __restrict__ bt,   // [S, 256]
    const int*   __restrict__ cl)   // [S]
{
    const int c = blockIdx.x, g = blockIdx.y, s = blockIdx.z;
    const int len = cl[s];
    if (c * CT >= len) return;
    const int n_tok = min(len - c * CT, CT);
    const int n_blk = (n_tok + BS - 1) / BS;
    const int tid = threadIdx.x;
    const int w = tid >> 5, l = tid & 31;

    __shared__ __align__(16) float q_s[HPG * DH];            // 2 KB
    __shared__ __align__(16) float ls[HPG * CT];             // 4 KB: logits then probs
    __shared__ __align__(16) float red_s[512 * RPITCH];      // 20 KB partials (8-blk groups)
    __shared__ float red[8], red2[8];
    __shared__ int bt_s[CB];

    if (tid < CB) bt_s[tid] = bt[s * MAXB + c * CB + tid];
    if (tid < 128)  // 512 floats of Q, coalesced float4
        ((float4*)q_s)[tid] =
            ((const float4*)(q + ((size_t)s * NHEAD + g * HPG) * DH))[tid];
    __syncthreads();

    // ===== Phase 1: K stream, lane-contiguous LDGs, 4-deep pipeline,
    //       Q read from smem (broadcast LDS), reduce in 8-block groups =======
    // Warp w owns K rows 2w,2w+1 of every block (2 contiguous 512B LDG.128s).
    // Lane l holds token l>>1, dims {16w+(l&1)*4..+4} U {16w+8+(l&1)*4..+4}.
    {
        const int koff = w * 256 + l * 4;
        const int tok = l >> 1;
        const int dbase = w * 16 + (l & 1) * 4;

        float4 kb[4][2];
#pragma unroll
        for (int p = 0; p < 4; p++) {
            const int bp = min(p, n_blk - 1);
            const float* sp = kc + ((size_t)bt_s[bp] * NKV + g) * 2048 + koff;
            kb[p][0] = *(const float4*)sp;
            kb[p][1] = *(const float4*)(sp + 128);
        }

#pragma unroll 1
        for (int gi = 0; gi < n_blk; gi += 8) {
#pragma unroll
            for (int uu = 0; uu < 8; uu++) {
                if (gi + uu < n_blk) {
                    const int slot = uu & 3;
                    const float4 a0 = kb[slot][0], a1 = kb[slot][1];
                    const int np = min(gi + uu + 4, n_blk - 1);
                    const float* sp = kc + ((size_t)bt_s[np] * NKV + g) * 2048 + koff;
                    kb[slot][0] = *(const float4*)sp;
                    kb[slot][1] = *(const float4*)(sp + 128);
#pragma unroll
                    for (int h = 0; h < HPG; h++) {
                        const float4 q0 = *(const float4*)&q_s[h * DH + dbase];
                        const float4 q1 = *(const float4*)&q_s[h * DH + dbase + 8];
                        float t = 0.f;
                        t = fmaf(a0.x, q0.x, t); t = fmaf(a0.y, q0.y, t);
                        t = fmaf(a0.z, q0.z, t); t = fmaf(a0.w, q0.w, t);
                        t = fmaf(a1.x, q1.x, t); t = fmaf(a1.y, q1.y, t);
                        t = fmaf(a1.z, q1.z, t); t = fmaf(a1.w, q1.w, t);
                        t += __shfl_xor_sync(0xffffffffu, t, 1);
                        if ((l & 1) == 0)
                            red_s[((uu * HPG + h) * BS + tok) * RPITCH + w] = t;
                    }
                }
            }
            __syncthreads();
#pragma unroll
            for (int e = tid; e < 512; e += 256) {
                const int blk_u = e >> 6;
                const int hh = (e >> 4) & 3;
                const int tk = e & 15;
                if (gi + blk_u < n_blk) {
                    const float* rp = &red_s[e * RPITCH];
                    float sum = 0.f;
#pragma unroll
                    for (int j = 0; j < 8; j++) sum += rp[j];
                    ls[hh * CT + (gi + blk_u) * BS + tk] = sum;
                }
            }
            __syncthreads();
        }
    }

    // ===== Hoisted V prologue: keep DRAM busy through the softmax ===========
    const int tl = (l & 3) * 4;
    const int d0 = w * 16 + (l >> 2);
    const int voff = w * 256 + l * 4;
    float4 vb[4][2];
#pragma unroll
    for (int p = 0; p < 4; p++) {
        const int bp = min(p, n_blk - 1);
        const float* sp = vc + ((size_t)bt_s[bp] * NKV + g) * 2048 + voff;
        vb[p][0] = *(const float4*)sp;
        vb[p][1] = *(const float4*)(sp + 128);
    }

    // ===== Phase 2: one-shot softmax over the chunk =========================
    const int h2 = tid >> 6;   // head (64 threads each)
    const int t2 = tid & 63;
    {
        float vals[4];
        float lmax = -1e30f;
#pragma unroll
        for (int k = 0; k < 4; k++) {
            const int tok = t2 + 64 * k;
            vals[k] = (tok < n_tok) ? ls[h2 * CT + tok] * QK_SCALE : -1e30f;
            lmax = fmaxf(lmax, vals[k]);
        }
#pragma unroll
        for (int o = 1; o < 32; o <<= 1)
            lmax = fmaxf(lmax, __shfl_xor_sync(0xffffffffu, lmax, o));
        if ((tid & 31) == 0) red[tid >> 5] = lmax;
        __syncthreads();
        const float m = fmaxf(red[h2 * 2], red[h2 * 2 + 1]);
        float lsum = 0.f;
#pragma unroll
        for (int k = 0; k < 4; k++) {
            const int tok = t2 + 64 * k;
            const float p = (tok < n_tok) ? __expf(vals[k] - m) : 0.f;
            ls[h2 * CT + tok] = p;
            lsum += p;
        }
#pragma unroll
        for (int o = 1; o < 32; o <<= 1)
            lsum += __shfl_xor_sync(0xffffffffu, lsum, o);
        if ((tid & 31) == 0) red2[tid >> 5] = lsum;
        __syncthreads();  // probs + red2 visible to all
        if (t2 == 0) {
            const int base = ((s * NKV + g) * NCHUNK + c) * HPG;
            g_pml[base + h2] = make_float2(m, red2[h2 * 2] + red2[h2 * 2 + 1]);
        }
    }

    // ===== Phase 3: V stream, lane-contiguous, 4-block register pipeline ====
    // Warp w owns dims d0 and d0+8; lane covers tokens (l&3)*4..+4.
    {
        float acc[HPG][2] = {};
        int i = 0;
#pragma unroll 1
        for (; i + 4 <= n_blk; i += 4) {
#pragma unroll
            for (int u = 0; u < 4; u++) {
                const float4 a0 = vb[u][0], a1 = vb[u][1];
                const int np = min(i + u + 4, n_blk - 1);
                const float* sp = vc + ((size_t)bt_s[np] * NKV + g) * 2048 + voff;
                vb[u][0] = *(const float4*)sp;
                vb[u][1] = *(const float4*)(sp + 128);
                const int pbase = (i + u) * BS + tl;
#pragma unroll
                for (int h = 0; h < HPG; h++) {
                    const float4 pv = *(const float4*)&ls[h * CT + pbase];
                    float a = acc[h][0];
                    a = fmaf(a0.x, pv.x, a); a = fmaf(a0.y, pv.y, a);
                    a = fmaf(a0.z, pv.z, a); a = fmaf(a0.w, pv.w, a);
                    acc[h][0] = a;
                    float b = acc[h][1];
                    b = fmaf(a1.x, pv.x, b); b = fmaf(a1.y, pv.y, b);
                    b = fmaf(a1.z, pv.z, b); b = fmaf(a1.w, pv.w, b);
                    acc[h][1] = b;
                }
            }
        }
#pragma unroll
        for (int u = 0; u < 3; u++) {
            if (i + u < n_blk) {
                const float4 a0 = vb[u][0], a1 = vb[u][1];
                const int pbase = (i + u) * BS + tl;
#pragma unroll
                for (int h = 0; h < HPG; h++) {
                    const float4 pv = *(const float4*)&ls[h * CT + pbase];
                    float a = acc[h][0];
                    a = fmaf(a0.x, pv.x, a); a = fmaf(a0.y, pv.y, a);
                    a = fmaf(a0.z, pv.z, a); a = fmaf(a0.w, pv.w, a);
                    acc[h][0] = a;
                    float b = acc[h][1];
                    b = fmaf(a1.x, pv.x, b); b = fmaf(a1.y, pv.y, b);
                    b = fmaf(a1.z, pv.z, b); b = fmaf(a1.w, pv.w, b);
                    acc[h][1] = b;
                }
            }
        }
        const int base = ((s * NKV + g) * NCHUNK + c) * HPG;
#pragma unroll
        for (int h = 0; h < HPG; h++) {
#pragma unroll
            for (int r = 0; r < 2; r++) {
                float v = acc[h][r];
                v += __shfl_xor_sync(0xffffffffu, v, 1);
                v += __shfl_xor_sync(0xffffffffu, v, 2);
                if ((l & 3) == 0)
                    g_pacc[(size_t)(base + h) * DH + d0 + r * 8] = v;
            }
        }
    }
}

__global__ __launch_bounds__(128) void pa_combine_kernel(
    const int* __restrict__ cl, float* __restrict__ out)
{
    const int h = blockIdx.x, s = blockIdx.y;
    const int g = h >> 2, hh = h & 3;
    const int tid = threadIdx.x;
    const int len = cl[s];
    const int nc = min(NCHUNK, (len + CT - 1) / CT);
    const int base = (s * NKV + g) * NCHUNK;

    __shared__ float w_s[NCHUNK];
    __shared__ float linv_s;

    if (tid < 32) {
        const int lane = tid;
        float2 ml = make_float2(-1e30f, 0.f);
        if (lane < nc) ml = g_pml[(base + lane) * HPG + hh];
        float M = ml.x;
#pragma unroll
        for (int o = 1; o < 32; o <<= 1)
            M = fmaxf(M, __shfl_xor_sync(0xffffffffu, M, o));
        const float wgt = (lane < nc) ? __expf(ml.x - M) : 0.f;
        float L = ml.y * wgt;
#pragma unroll
        for (int o = 1; o < 32; o <<= 1)
            L += __shfl_xor_sync(0xffffffffu, L, o);
        if (lane < NCHUNK) w_s[lane] = wgt;
        if (lane == 0) linv_s = 1.f / L;
    }
    __syncthreads();

    const int d = tid;
    float o = 0.f;
#pragma unroll
    for (int c = 0; c < NCHUNK; c++) {
        const float pa = (c < nc) ? g_pacc[(size_t)((base + c) * HPG + hh) * DH + d] : 0.f;
        o += pa * w_s[c];
    }
    out[((size_t)s * NHEAD + h) * DH + d] = o * linv_s;
}

extern "C" void kernel_launch(void* const* d_in, const int* in_sizes, int n_in,
                              void* d_out, int out_size)
{
    const float* q  = (const float*)d_in[0];
    const float* kc = (const float*)d_in[1];
    const float* vc = (const float*)d_in[2];
    const int*   bt = (const int*)d_in[3];
    const int*   cl = (const int*)d_in[4];
    float* out = (float*)d_out;

    dim3 grid1(NCHUNK, NKV, NSEQ);   // 16 x 8 x 32 = 4096 CTAs
    pa_chunk_kernel<<<grid1, 256>>>(q, kc, vc, bt, cl);
    dim3 grid2(NHEAD, NSEQ);         // 32 x 32 = 1024 CTAs
    pa_combine_kernel<<<grid2, 128>>>(cl, out);
}